// round 5
// baseline (speedup 1.0000x reference)
#include <cuda_runtime.h>
#include <cstdint>

// Problem constants: B=512, T=2048, I=4, H=100, O=1
#define HDIM      100
#define TLEN      2048
#define WARPS     4      // warps per CTA = batches per CTA
#define BLOCK_T   128
#define NBLOCKS   128    // 128 * 4 = 512 batches
#define ALANES    25     // active lanes per warp (25 * 4 rows = 100)
#define PADH      112    // padded h row in smem (16B aligned)

// ---- packed fp32x2 ops (Blackwell FFMA2 path, only reachable via PTX) ----
__device__ __forceinline__ unsigned long long ffma2(unsigned long long a,
                                                    unsigned long long b,
                                                    unsigned long long c) {
    unsigned long long d;
    asm("fma.rn.f32x2 %0, %1, %2, %3;" : "=l"(d) : "l"(a), "l"(b), "l"(c));
    return d;
}
__device__ __forceinline__ unsigned long long fmul2(unsigned long long a,
                                                    unsigned long long b) {
    unsigned long long d;
    asm("mul.rn.f32x2 %0, %1, %2;" : "=l"(d) : "l"(a), "l"(b));
    return d;
}
__device__ __forceinline__ float hsum2(unsigned long long a) {
    unsigned int lo, hi;
    asm("mov.b64 {%0, %1}, %2;" : "=r"(lo), "=r"(hi) : "l"(a));
    return __uint_as_float(lo) + __uint_as_float(hi);
}

// tanh(x) = 1 - 2/(exp2(2*log2e*x)+1): FMUL + EX2 + FADD + RCP + FFMA
// (~1e-7 abs error; validated at rel_err 9.6e-7 in R2 over 2048 steps)
__device__ __forceinline__ float fast_tanh(float x) {
    float e, r;
    asm("ex2.approx.f32 %0, %1;" : "=f"(e) : "f"(x * 2.8853900817779268f));
    asm("rcp.approx.f32 %0, %1;" : "=f"(r) : "f"(e + 1.0f));
    return fmaf(-2.0f, r, 1.0f);
}

__global__ void __launch_bounds__(BLOCK_T, 1)
crnn_kernel(const float* __restrict__ x,      // [512, 2048, 4]
            const float* __restrict__ W_ih,   // [100, 4]
            const float* __restrict__ W_hh,   // [100, 100]
            const float* __restrict__ W_fc,   // [1, 100]
            const float* __restrict__ b_fc,   // [1]
            float* __restrict__ out)          // [512, 2048, 1]
{
    // double-buffered hidden state, one row per warp (= per batch)
    __shared__ __align__(16) float hbuf[2][WARPS][PADH];

    const int tid  = threadIdx.x;
    const int wid  = tid >> 5;
    const int lane = tid & 31;
    const int bg   = blockIdx.x * WARPS + wid;   // global batch for this warp

    // zero both h buffers (h0 = 0); only block-wide barrier in the kernel
    for (int i = tid; i < 2 * WARPS * PADH; i += BLOCK_T)
        ((float*)hbuf)[i] = 0.0f;
    __syncthreads();

    // lane L (<25) owns rows base..base+3; lanes 25..31 compute discarded work
    const bool active = (lane < ALANES);
    const int  base   = active ? lane * 4 : (HDIM - 4);  // clamp: safe loads

    // W_hh rows -> 4 x 50 fp32x2 pairs = 200 registers
    unsigned long long w[4][50];
    #pragma unroll
    for (int r = 0; r < 4; r++) {
        const ulonglong2* wrow =
            reinterpret_cast<const ulonglong2*>(W_hh + (base + r) * HDIM);
        #pragma unroll
        for (int j = 0; j < 25; j++) {
            ulonglong2 v = wrow[j];
            w[r][2 * j]     = v.x;   // (W[row][4j],   W[row][4j+1])
            w[r][2 * j + 1] = v.y;   // (W[row][4j+2], W[row][4j+3])
        }
    }

    // W_ih rows (4 floats each) as fp32x2 pairs
    unsigned long long wih[4][2];
    #pragma unroll
    for (int r = 0; r < 4; r++) {
        ulonglong2 v = *reinterpret_cast<const ulonglong2*>(W_ih + (base + r) * 4);
        wih[r][0] = v.x;
        wih[r][1] = v.y;
    }

    // W_fc slice for this lane's 4 rows (zeroed for inactive lanes)
    float4 wf = *reinterpret_cast<const float4*>(W_fc + base);
    if (!active) { wf.x = wf.y = wf.z = wf.w = 0.0f; }
    const float bias = b_fc[0];

    // x[b] rows: 16B per timestep, broadcast across the warp
    const ulonglong2* xp =
        reinterpret_cast<const ulonglong2*>(x) + (size_t)bg * TLEN;
    float* op = out + (size_t)bg * TLEN;

    float* const h0 = &hbuf[0][wid][0];
    float* const h1 = &hbuf[1][wid][0];

    ulonglong2 xcur = xp[0];

    #pragma unroll 1
    for (int t = 0; t < TLEN; t++) {
        // prefetch next timestep's x (latency hidden under the matvec)
        const int tn = (t < TLEN - 1) ? (t + 1) : t;
        ulonglong2 xnext = xp[tn];

        const float* hb = (t & 1) ? h1 : h0;
        float*       hw = (t & 1) ? h0 : h1;

        // accumulators init = input projection for each of the 4 rows
        unsigned long long acc[4];
        #pragma unroll
        for (int r = 0; r < 4; r++) {
            acc[r] = fmul2(xcur.x, wih[r][0]);
            acc[r] = ffma2(xcur.y, wih[r][1], acc[r]);
        }

        // matvec: 25 broadcast LDS.128, each feeding 8 FFMA2 (4 rows x 2)
        const ulonglong2* hv = reinterpret_cast<const ulonglong2*>(hb);
        #pragma unroll
        for (int j = 0; j < 25; j++) {
            ulonglong2 h4 = hv[j];
            #pragma unroll
            for (int r = 0; r < 4; r++) {
                acc[r] = ffma2(h4.x, w[r][2 * j], acc[r]);
                acc[r] = ffma2(h4.y, w[r][2 * j + 1], acc[r]);
            }
        }

        // per-row: horizontal sum + tanh
        float hn0 = fast_tanh(hsum2(acc[0]));
        float hn1 = fast_tanh(hsum2(acc[1]));
        float hn2 = fast_tanh(hsum2(acc[2]));
        float hn3 = fast_tanh(hsum2(acc[3]));

        // publish h_t: one STS.128 per active lane (rows 4L..4L+3 contiguous)
        if (active) {
            float4 hv4 = make_float4(hn0, hn1, hn2, hn3);
            *reinterpret_cast<float4*>(hw + base) = hv4;
        }

        // output projection: dead-end computation, latency hides under next step
        float p = 0.0f;
        if (active) {
            p = hn0 * wf.x;
            p = fmaf(hn1, wf.y, p);
            p = fmaf(hn2, wf.z, p);
            p = fmaf(hn3, wf.w, p);
        }
        p += __shfl_xor_sync(0xFFFFFFFFu, p, 1);
        p += __shfl_xor_sync(0xFFFFFFFFu, p, 2);
        p += __shfl_xor_sync(0xFFFFFFFFu, p, 4);
        p += __shfl_xor_sync(0xFFFFFFFFu, p, 8);
        p += __shfl_xor_sync(0xFFFFFFFFu, p, 16);
        if (lane == 0)
            op[t] = p + bias;

        xcur = xnext;
        __syncwarp();   // order this step's STS before next step's LDS
    }
}

extern "C" void kernel_launch(void* const* d_in, const int* in_sizes, int n_in,
                              void* d_out, int out_size) {
    const float* x    = (const float*)d_in[0];  // [512,2048,4]
    const float* W_ih = (const float*)d_in[1];  // [100,4]
    const float* W_hh = (const float*)d_in[2];  // [100,100]
    const float* W_fc = (const float*)d_in[3];  // [1,100]
    const float* b_fc = (const float*)d_in[4];  // [1]
    float* out = (float*)d_out;                 // [512,2048,1]

    crnn_kernel<<<NBLOCKS, BLOCK_T>>>(x, W_ih, W_hh, W_fc, b_fc, out);
}

// round 6
// speedup vs baseline: 1.7361x; 1.7361x over previous
#include <cuda_runtime.h>
#include <cstdint>

// Problem constants: B=512, T=2048, I=4, H=100, O=1
#define HDIM    100
#define TLEN    2048
#define NBATCH  2       // batch groups per CTA
#define GSIZE   128     // threads per group = 4 whole warps
#define BLOCK_T 256
#define NBLOCKS 256     // 256 * 2 = 512 batches; single wave at 2 CTAs/SM
#define PADH    112     // padded h row (16B aligned)

// ---- packed fp32x2 ops (Blackwell FFMA2 path, only reachable via PTX) ----
__device__ __forceinline__ unsigned long long ffma2(unsigned long long a,
                                                    unsigned long long b,
                                                    unsigned long long c) {
    unsigned long long d;
    asm("fma.rn.f32x2 %0, %1, %2, %3;" : "=l"(d) : "l"(a), "l"(b), "l"(c));
    return d;
}
__device__ __forceinline__ unsigned long long fmul2(unsigned long long a,
                                                    unsigned long long b) {
    unsigned long long d;
    asm("mul.rn.f32x2 %0, %1, %2;" : "=l"(d) : "l"(a), "l"(b));
    return d;
}
__device__ __forceinline__ unsigned long long fadd2(unsigned long long a,
                                                    unsigned long long b) {
    unsigned long long d;
    asm("add.rn.f32x2 %0, %1, %2;" : "=l"(d) : "l"(a), "l"(b));
    return d;
}
__device__ __forceinline__ float hsum2(unsigned long long a) {
    unsigned int lo, hi;
    asm("mov.b64 {%0, %1}, %2;" : "=r"(lo), "=r"(hi) : "l"(a));
    return __uint_as_float(lo) + __uint_as_float(hi);
}

// tanh(x) = 1 - 2/(exp2(2*log2e*x)+1): FMUL + EX2 + FADD + RCP + FFMA
// (validated: rel_err ~1e-6 over 2048 steps in R2/R4)
__device__ __forceinline__ float fast_tanh(float x) {
    float e, r;
    asm("ex2.approx.f32 %0, %1;" : "=f"(e) : "f"(x * 2.8853900817779268f));
    asm("rcp.approx.f32 %0, %1;" : "=f"(r) : "f"(e + 1.0f));
    return fmaf(-2.0f, r, 1.0f);
}

__global__ void __launch_bounds__(BLOCK_T, 2)
crnn_kernel(const float* __restrict__ x,      // [512, 2048, 4]
            const float* __restrict__ W_ih,   // [100, 4]
            const float* __restrict__ W_hh,   // [100, 100]
            const float* __restrict__ W_fc,   // [1, 100]
            const float* __restrict__ b_fc,   // [1]
            float* __restrict__ out)          // [512, 2048, 1]
{
    // double-buffered hidden state, one row per batch group
    __shared__ __align__(16) float hbuf[2][NBATCH][PADH];
    // double-buffered per-warp output-projection partials
    __shared__ float ppart[2][NBATCH][4];

    const int tid   = threadIdx.x;
    const int g     = tid >> 7;        // batch group 0..1 (4 whole warps each)
    const int hh    = tid & 127;       // h index within group; >=100 inactive
    const int wig   = (tid >> 5) & 3;  // warp index within group
    const int lane  = tid & 31;
    const bool active = (hh < HDIM);
    const int row   = active ? hh : (HDIM - 1);   // clamp for safe loads
    const int bg    = blockIdx.x * NBATCH + g;

    // zero both h buffers (h0 = 0)
    for (int i = tid; i < 2 * NBATCH * PADH; i += BLOCK_T)
        ((float*)hbuf)[i] = 0.0f;

    // W_hh row -> 50 fp32x2 pairs = 100 registers (paired over K)
    unsigned long long w[50];
    {
        const ulonglong2* wrow =
            reinterpret_cast<const ulonglong2*>(W_hh + row * HDIM);
        #pragma unroll
        for (int j = 0; j < 25; j++) {
            ulonglong2 v = wrow[j];
            w[2 * j]     = v.x;
            w[2 * j + 1] = v.y;
        }
    }

    // W_ih row (4 floats) as two fp32x2 pairs
    const ulonglong2 wihv =
        *reinterpret_cast<const ulonglong2*>(W_ih + row * 4);

    // output-projection weight for this thread's h element
    const float wfc  = active ? W_fc[hh] : 0.0f;
    const float bias = b_fc[0];

    const ulonglong2* xp =
        reinterpret_cast<const ulonglong2*>(x) + (size_t)bg * TLEN;
    float* op = out + (size_t)bg * TLEN;

    __syncthreads();                   // init barrier

    ulonglong2 xcur = xp[0];

    #pragma unroll 1
    for (int t = 0; t < TLEN; t++) {
        // ---- finish step t-1's output projection (pipelined past barrier)
        if (t > 0 && hh == 0) {
            const float* pp = ppart[(t - 1) & 1][g];
            op[t - 1] = pp[0] + pp[1] + pp[2] + pp[3] + bias;
        }

        // prefetch next timestep's x
        const int tn = (t < TLEN - 1) ? (t + 1) : t;
        ulonglong2 xnext = xp[tn];

        const int cur = t & 1;

        // accumulator init = input projection xp_t
        unsigned long long a0 = fmul2(xcur.x, wihv.x);
        a0 = ffma2(xcur.y, wihv.y, a0);
        unsigned long long a1 = 0ull, a2 = 0ull, a3 = 0ull;

        // matvec: 25x broadcast LDS.128 + 50x FFMA2 (conflict-free: one
        // batch row per warp)
        const ulonglong2* hv =
            reinterpret_cast<const ulonglong2*>(&hbuf[cur][g][0]);
        #pragma unroll
        for (int j = 0; j < 25; j++) {
            ulonglong2 h4 = hv[j];
            if (j & 1) {
                a2 = ffma2(h4.x, w[2 * j], a2);
                a3 = ffma2(h4.y, w[2 * j + 1], a3);
            } else {
                a0 = ffma2(h4.x, w[2 * j], a0);
                a1 = ffma2(h4.y, w[2 * j + 1], a1);
            }
        }

        const float pre  = hsum2(fadd2(fadd2(a0, a1), fadd2(a2, a3)));
        const float hnew = fast_tanh(pre);

        if (active)
            hbuf[cur ^ 1][g][hh] = hnew;

        // output projection partial: warp reduce, lane 0 -> smem
        float p = active ? hnew * wfc : 0.0f;
        p += __shfl_xor_sync(0xFFFFFFFFu, p, 1);
        p += __shfl_xor_sync(0xFFFFFFFFu, p, 2);
        p += __shfl_xor_sync(0xFFFFFFFFu, p, 4);
        p += __shfl_xor_sync(0xFFFFFFFFu, p, 8);
        p += __shfl_xor_sync(0xFFFFFFFFu, p, 16);
        if (lane == 0)
            ppart[cur][g][wig] = p;

        xcur = xnext;
        __syncthreads();               // h_{t+1} buffer + partials published
    }

    // flush last timestep's output
    if (hh == 0) {
        const float* pp = ppart[(TLEN - 1) & 1][g];
        op[TLEN - 1] = pp[0] + pp[1] + pp[2] + pp[3] + bias;
    }
}

extern "C" void kernel_launch(void* const* d_in, const int* in_sizes, int n_in,
                              void* d_out, int out_size) {
    const float* x    = (const float*)d_in[0];  // [512,2048,4]
    const float* W_ih = (const float*)d_in[1];  // [100,4]
    const float* W_hh = (const float*)d_in[2];  // [100,100]
    const float* W_fc = (const float*)d_in[3];  // [1,100]
    const float* b_fc = (const float*)d_in[4];  // [1]
    float* out = (float*)d_out;                 // [512,2048,1]

    crnn_kernel<<<NBLOCKS, BLOCK_T>>>(x, W_ih, W_hh, W_fc, b_fc, out);
}